// round 10
// baseline (speedup 1.0000x reference)
#include <cuda_runtime.h>

// SSIM loss: pred/target fp32 (8,8,3,256,256) -> scalar 1 - mean(ssim_map)
// 192 planes of 256x256. Depthwise 11x11 Gaussian (sigma=1.5), separable.
//
// Sum/diff basis: s = x+y, d = x-y. Four convolutions (s, d, s^2, d^2):
//   A = conv(s), B = conv(d), S1 = conv(s^2), S2 = conv(d^2)
//   4 mu_xy = A^2 - B^2;  2(mu_x^2+mu_y^2) = A^2 + B^2
//   4 Sxy   = S1 - S2;    2(Sxx+Syy)       = S1 + S2
//
// 32x64 output tiles (taller tile halves y-halo overhead), 512 threads,
// 3 blocks/SM via dynamic smem (66.3 KB). Global reduction: fixed-point u64
// RED.ADD (associative -> deterministic; fire-and-forget -> no per-block
// fence, which measured +20us at this grid).

#define HW       256
#define PLANE    (HW * HW)
#define NPLANES  192
#define TILES_X  8
#define TILES_Y  4
#define NTHREADS 512
#define NPIX     12582912.0                       // 192*256*256
#define FXSCALE  4294967296.0                     // 2^32

#define TILE_H   64
#define ROWW     48                               // staged raw row width (floats)
#define NROWS    74                               // 64 out + 2*5 halo

#define SINT_SZ  (NROWS * 32)                     // 2368 floats per quantity
#define SRAW_SZ  (NROWS * ROWW)                   // 3552 floats per array
#define SMEM_FLOATS (4 * SINT_SZ + 2 * SRAW_SZ)   // 16576
#define SMEM_BYTES  (SMEM_FLOATS * 4)             // 66304

__device__ unsigned long long g_isum = 0ULL;      // reset by finalize (replay-safe)

// Normalized Gaussian weights for ws=11, sigma=1.5.
#define GW0 0.00102838f
#define GW1 0.00759872f
#define GW2 0.03600084f
#define GW3 0.10936034f
#define GW4 0.21300566f
#define GW5 0.26601220f

__global__ __launch_bounds__(NTHREADS, 3) void ssim_main(
    const float* __restrict__ pred, const float* __restrict__ targ)
{
    extern __shared__ float dyn[];
    float* const s_int = dyn;                     // [4][NROWS*32]
    float* const s_raw = dyn + 4 * SINT_SZ;       // [2][NROWS*ROWW]
    __shared__ float s_red[16];

    const int tid = threadIdx.x;
    const int ox = blockIdx.x * 32;
    const int oy = blockIdx.y * TILE_H;
    const int plane = blockIdx.z;
    const float* __restrict__ px = pred + (size_t)plane * PLANE;
    const float* __restrict__ py = targ + (size_t)plane * PLANE;

    const float W[11] = {GW0, GW1, GW2, GW3, GW4, GW5, GW4, GW3, GW2, GW1, GW0};

    // ---- Phase 0: coalesced float4 staging of s = x+y, d = x-y ----
    // 74 rows x 12 float4 = 888 tasks. smem col j <-> gmem col ox-8+j.
    for (int task = tid; task < NROWS * 12; task += NTHREADS) {
        const int r  = task / 12;
        const int v  = task - r * 12;
        const int gy = oy + r - 5;
        const int gx = ox - 8 + 4 * v;

        float4 xv = make_float4(0.f, 0.f, 0.f, 0.f);
        float4 yv = xv;
        if ((unsigned)gy < (unsigned)HW && (unsigned)gx < (unsigned)HW) {
            xv = __ldg(reinterpret_cast<const float4*>(px + gy * HW + gx));
            yv = __ldg(reinterpret_cast<const float4*>(py + gy * HW + gx));
        }
        const int o = r * ROWW + 4 * v;
        *reinterpret_cast<float4*>(&s_raw[o]) =
            make_float4(xv.x + yv.x, xv.y + yv.y, xv.z + yv.z, xv.w + yv.w);
        *reinterpret_cast<float4*>(&s_raw[SRAW_SZ + o]) =
            make_float4(xv.x - yv.x, xv.y - yv.y, xv.z - yv.z, xv.w - yv.w);
    }
    __syncthreads();

    // ---- Phase A: horizontal conv of s, d, s^2, d^2 ----
    // 74 rows x 8 col-groups (4 outputs) = 592 tasks.
    for (int task = tid; task < NROWS * 8; task += NTHREADS) {
        const int r  = task >> 3;
        const int c0 = (task & 7) * 4;
        const int base = r * ROWW + c0;
        float t[20], v[14];

        // s
        #pragma unroll
        for (int vi = 0; vi < 5; vi++)
            *reinterpret_cast<float4*>(&t[4 * vi]) =
                *reinterpret_cast<const float4*>(&s_raw[base + 4 * vi]);
        {
            float a0 = 0.f, a1 = 0.f, a2 = 0.f, a3 = 0.f;
            #pragma unroll
            for (int k = 0; k < 11; k++) {
                a0 = fmaf(W[k], t[3 + k],     a0);
                a1 = fmaf(W[k], t[3 + k + 1], a1);
                a2 = fmaf(W[k], t[3 + k + 2], a2);
                a3 = fmaf(W[k], t[3 + k + 3], a3);
            }
            *reinterpret_cast<float4*>(&s_int[0 * SINT_SZ + r * 32 + c0]) =
                make_float4(a0, a1, a2, a3);
        }
        // s^2
        #pragma unroll
        for (int i = 0; i < 14; i++) v[i] = t[3 + i] * t[3 + i];
        {
            float a0 = 0.f, a1 = 0.f, a2 = 0.f, a3 = 0.f;
            #pragma unroll
            for (int k = 0; k < 11; k++) {
                a0 = fmaf(W[k], v[k],     a0);
                a1 = fmaf(W[k], v[k + 1], a1);
                a2 = fmaf(W[k], v[k + 2], a2);
                a3 = fmaf(W[k], v[k + 3], a3);
            }
            *reinterpret_cast<float4*>(&s_int[2 * SINT_SZ + r * 32 + c0]) =
                make_float4(a0, a1, a2, a3);
        }
        // d
        #pragma unroll
        for (int vi = 0; vi < 5; vi++)
            *reinterpret_cast<float4*>(&t[4 * vi]) =
                *reinterpret_cast<const float4*>(&s_raw[SRAW_SZ + base + 4 * vi]);
        {
            float a0 = 0.f, a1 = 0.f, a2 = 0.f, a3 = 0.f;
            #pragma unroll
            for (int k = 0; k < 11; k++) {
                a0 = fmaf(W[k], t[3 + k],     a0);
                a1 = fmaf(W[k], t[3 + k + 1], a1);
                a2 = fmaf(W[k], t[3 + k + 2], a2);
                a3 = fmaf(W[k], t[3 + k + 3], a3);
            }
            *reinterpret_cast<float4*>(&s_int[1 * SINT_SZ + r * 32 + c0]) =
                make_float4(a0, a1, a2, a3);
        }
        // d^2
        #pragma unroll
        for (int i = 0; i < 14; i++) v[i] = t[3 + i] * t[3 + i];
        {
            float a0 = 0.f, a1 = 0.f, a2 = 0.f, a3 = 0.f;
            #pragma unroll
            for (int k = 0; k < 11; k++) {
                a0 = fmaf(W[k], v[k],     a0);
                a1 = fmaf(W[k], v[k + 1], a1);
                a2 = fmaf(W[k], v[k + 2], a2);
                a3 = fmaf(W[k], v[k + 3], a3);
            }
            *reinterpret_cast<float4*>(&s_int[3 * SINT_SZ + r * 32 + c0]) =
                make_float4(a0, a1, a2, a3);
        }
    }
    __syncthreads();

    // ---- Phase B+C merged: vertical conv (4 rows x 4 quantities in regs)
    // then SSIM directly. 512 tasks: tid -> (rowgroup of 4, col).
    float lsum = 0.0f;
    {
        const int rg = tid >> 5;          // 0..15
        const int c  = tid & 31;
        const int r0 = rg * 4;

        float res[4][4];
        #pragma unroll
        for (int q = 0; q < 4; q++) {
            float v[14];
            #pragma unroll
            for (int k = 0; k < 14; k++) v[k] = s_int[q * SINT_SZ + (r0 + k) * 32 + c];
            #pragma unroll
            for (int j = 0; j < 4; j++) {
                float a = 0.f;
                #pragma unroll
                for (int k = 0; k < 11; k++) a = fmaf(W[k], v[j + k], a);
                res[q][j] = a;
            }
        }

        #pragma unroll
        for (int j = 0; j < 4; j++) {
            const float A  = res[0][j];
            const float B  = res[1][j];
            const float S1 = res[2][j];
            const float S2 = res[3][j];

            const float A2 = A * A;
            const float B2 = B * B;
            const float mxy  = 0.25f * (A2 - B2);          // mu_x * mu_y
            const float msum = 0.50f * (A2 + B2);          // mu_x^2 + mu_y^2
            const float sxy  = 0.25f * (S1 - S2) - mxy;    // sigma_xy
            const float ssum = fmaxf(0.50f * (S1 + S2) - msum, 0.0f);

            const float num = (2.0f * mxy + 1e-4f) * (2.0f * sxy + 9e-4f);
            const float den = (msum + 1e-4f) * (ssum + 9e-4f);
            float s = num / (den + 1e-8f);
            if (!isfinite(s)) s = 0.0f;
            lsum += s;
        }
    }

    #pragma unroll
    for (int o = 16; o > 0; o >>= 1)
        lsum += __shfl_down_sync(0xffffffffu, lsum, o);
    if ((tid & 31) == 0) s_red[tid >> 5] = lsum;
    __syncthreads();
    if (tid == 0) {
        float v = 0.0f;
        #pragma unroll
        for (int w = 0; w < 16; w++) v += s_red[w];
        // Fixed-point RED.ADD.u64: fire-and-forget, associative, deterministic.
        atomicAdd(&g_isum, (unsigned long long)__double2ll_rn((double)v * FXSCALE));
    }
}

// Trivial finalize: one load, one store, reset accumulator for graph replay.
__global__ void ssim_finalize(float* __restrict__ out)
{
    const double s = (double)g_isum * (1.0 / FXSCALE);
    out[0] = 1.0f - (float)(s / NPIX);
    g_isum = 0ULL;
}

extern "C" void kernel_launch(void* const* d_in, const int* in_sizes, int n_in,
                              void* d_out, int out_size)
{
    const float* pred = (const float*)d_in[0];
    const float* targ = (const float*)d_in[1];
    // Idempotent attribute set (not a stream op; safe under graph capture).
    cudaFuncSetAttribute(ssim_main, cudaFuncAttributeMaxDynamicSharedMemorySize,
                         SMEM_BYTES);
    dim3 grid(TILES_X, TILES_Y, NPLANES);
    ssim_main<<<grid, NTHREADS, SMEM_BYTES>>>(pred, targ);
    ssim_finalize<<<1, 1>>>((float*)d_out);
}

// round 11
// speedup vs baseline: 1.0257x; 1.0257x over previous
#include <cuda_runtime.h>

// SSIM loss: pred/target fp32 (8,8,3,256,256) -> scalar 1 - mean(ssim_map)
// 192 planes of 256x256. Depthwise 11x11 Gaussian (sigma=1.5), separable.
//
// Sum/diff basis: s = x+y, d = x-y. Four convolutions (s, d, s^2, d^2):
//   A = conv(s), B = conv(d), S1 = conv(s^2), S2 = conv(d^2)
//   4 mu_xy = A^2 - B^2;  2(mu_x^2+mu_y^2) = A^2 + B^2
//   4 Sxy   = S1 - S2;    2(Sxx+Syy)       = S1 + S2
//
// Global reduction: fixed-point u64 RED.ADD (associative -> deterministic,
// fire-and-forget -> no per-block fence; a fence/release costs +20us here).

#define HW       256
#define PLANE    (HW * HW)
#define NPLANES  192
#define TILES_X  8
#define TILES_Y  8
#define NTHREADS 256
#define NPIX     12582912.0                       // 192*256*256
#define FXSCALE  4294967296.0                     // 2^32

#define ROWW     48                               // staged raw row width (floats)
#define NROWS    42                               // 32 out + 2*5 halo

__device__ unsigned long long g_isum = 0ULL;      // reset by finalize (replay-safe)

// Normalized Gaussian weights for ws=11, sigma=1.5.
#define GW0 0.00102838f
#define GW1 0.00759872f
#define GW2 0.03600084f
#define GW3 0.10936034f
#define GW4 0.21300566f
#define GW5 0.26601220f

__global__ __launch_bounds__(NTHREADS, 6) void ssim_main(
    const float* __restrict__ pred, const float* __restrict__ targ)
{
    // Horizontal-conv intermediates: 4 quantities x 42 rows x 32 cols (21504 B)
    __shared__ float s_int[4][NROWS * 32];
    __shared__ float s_raw[2][NROWS * ROWW];      // 16128 B (s, d), zero-padded
    __shared__ float s_red[8];

    const int tid = threadIdx.x;
    const int ox = blockIdx.x * 32;
    const int oy = blockIdx.y * 32;
    const int plane = blockIdx.z;
    const float* __restrict__ px = pred + (size_t)plane * PLANE;
    const float* __restrict__ py = targ + (size_t)plane * PLANE;

    const float W[11] = {GW0, GW1, GW2, GW3, GW4, GW5, GW4, GW3, GW2, GW1, GW0};

    // ---- Phase 0: coalesced float4 staging of s = x+y, d = x-y ----
    // 42 rows x 12 float4 = 504 tasks. smem col j <-> gmem col ox-8+j.
    for (int task = tid; task < NROWS * 12; task += NTHREADS) {
        const int r  = task / 12;
        const int v  = task - r * 12;
        const int gy = oy + r - 5;
        const int gx = ox - 8 + 4 * v;

        float4 xv = make_float4(0.f, 0.f, 0.f, 0.f);
        float4 yv = xv;
        if ((unsigned)gy < (unsigned)HW && (unsigned)gx < (unsigned)HW) {
            xv = __ldg(reinterpret_cast<const float4*>(px + gy * HW + gx));
            yv = __ldg(reinterpret_cast<const float4*>(py + gy * HW + gx));
        }
        const int o = r * ROWW + 4 * v;
        *reinterpret_cast<float4*>(&s_raw[0][o]) =
            make_float4(xv.x + yv.x, xv.y + yv.y, xv.z + yv.z, xv.w + yv.w);
        *reinterpret_cast<float4*>(&s_raw[1][o]) =
            make_float4(xv.x - yv.x, xv.y - yv.y, xv.z - yv.z, xv.w - yv.w);
    }
    __syncthreads();

    // ---- Phase A: horizontal conv of s, d, s^2, d^2 ----
    // 42 rows x 8 col-groups (4 outputs) = 336 tasks.
    for (int task = tid; task < NROWS * 8; task += NTHREADS) {
        const int r  = task >> 3;
        const int c0 = (task & 7) * 4;
        const int base = r * ROWW + c0;
        float t[20], v[14];

        // s
        #pragma unroll
        for (int vi = 0; vi < 5; vi++)
            *reinterpret_cast<float4*>(&t[4 * vi]) =
                *reinterpret_cast<const float4*>(&s_raw[0][base + 4 * vi]);
        {
            float a0 = 0.f, a1 = 0.f, a2 = 0.f, a3 = 0.f;
            #pragma unroll
            for (int k = 0; k < 11; k++) {
                a0 = fmaf(W[k], t[3 + k],     a0);
                a1 = fmaf(W[k], t[3 + k + 1], a1);
                a2 = fmaf(W[k], t[3 + k + 2], a2);
                a3 = fmaf(W[k], t[3 + k + 3], a3);
            }
            *reinterpret_cast<float4*>(&s_int[0][r * 32 + c0]) = make_float4(a0, a1, a2, a3);
        }
        // s^2
        #pragma unroll
        for (int i = 0; i < 14; i++) v[i] = t[3 + i] * t[3 + i];
        {
            float a0 = 0.f, a1 = 0.f, a2 = 0.f, a3 = 0.f;
            #pragma unroll
            for (int k = 0; k < 11; k++) {
                a0 = fmaf(W[k], v[k],     a0);
                a1 = fmaf(W[k], v[k + 1], a1);
                a2 = fmaf(W[k], v[k + 2], a2);
                a3 = fmaf(W[k], v[k + 3], a3);
            }
            *reinterpret_cast<float4*>(&s_int[2][r * 32 + c0]) = make_float4(a0, a1, a2, a3);
        }
        // d
        #pragma unroll
        for (int vi = 0; vi < 5; vi++)
            *reinterpret_cast<float4*>(&t[4 * vi]) =
                *reinterpret_cast<const float4*>(&s_raw[1][base + 4 * vi]);
        {
            float a0 = 0.f, a1 = 0.f, a2 = 0.f, a3 = 0.f;
            #pragma unroll
            for (int k = 0; k < 11; k++) {
                a0 = fmaf(W[k], t[3 + k],     a0);
                a1 = fmaf(W[k], t[3 + k + 1], a1);
                a2 = fmaf(W[k], t[3 + k + 2], a2);
                a3 = fmaf(W[k], t[3 + k + 3], a3);
            }
            *reinterpret_cast<float4*>(&s_int[1][r * 32 + c0]) = make_float4(a0, a1, a2, a3);
        }
        // d^2
        #pragma unroll
        for (int i = 0; i < 14; i++) v[i] = t[3 + i] * t[3 + i];
        {
            float a0 = 0.f, a1 = 0.f, a2 = 0.f, a3 = 0.f;
            #pragma unroll
            for (int k = 0; k < 11; k++) {
                a0 = fmaf(W[k], v[k],     a0);
                a1 = fmaf(W[k], v[k + 1], a1);
                a2 = fmaf(W[k], v[k + 2], a2);
                a3 = fmaf(W[k], v[k + 3], a3);
            }
            *reinterpret_cast<float4*>(&s_int[3][r * 32 + c0]) = make_float4(a0, a1, a2, a3);
        }
    }
    __syncthreads();

    // ---- Phase B+C merged: vertical conv (4 rows x 4 quantities in regs)
    // then SSIM directly. 256 tasks: tid -> (rowgroup of 4, col).
    float lsum = 0.0f;
    {
        const int rg = tid >> 5;          // 0..7
        const int c  = tid & 31;
        const int r0 = rg * 4;

        float res[4][4];
        #pragma unroll
        for (int q = 0; q < 4; q++) {
            float v[14];
            #pragma unroll
            for (int k = 0; k < 14; k++) v[k] = s_int[q][(r0 + k) * 32 + c];
            #pragma unroll
            for (int j = 0; j < 4; j++) {
                float a = 0.f;
                #pragma unroll
                for (int k = 0; k < 11; k++) a = fmaf(W[k], v[j + k], a);
                res[q][j] = a;
            }
        }

        #pragma unroll
        for (int j = 0; j < 4; j++) {
            const float A  = res[0][j];
            const float B  = res[1][j];
            const float S1 = res[2][j];
            const float S2 = res[3][j];

            const float A2 = A * A;
            const float B2 = B * B;
            const float mxy  = 0.25f * (A2 - B2);          // mu_x * mu_y
            const float msum = 0.50f * (A2 + B2);          // mu_x^2 + mu_y^2
            const float sxy  = 0.25f * (S1 - S2) - mxy;    // sigma_xy
            const float ssum = fmaxf(0.50f * (S1 + S2) - msum, 0.0f);

            // den >= C1*C2 = 9e-8 > 0 always (msum,ssum >= 0), and num is
            // bounded for bounded inputs: the reference's nan_to_num is a
            // mathematical no-op here. Fast divide: 2^-21 rel err << budget.
            const float num = (2.0f * mxy + 1e-4f) * (2.0f * sxy + 9e-4f);
            const float den = (msum + 1e-4f) * (ssum + 9e-4f);
            lsum += __fdividef(num, den + 1e-8f);
        }
    }

    #pragma unroll
    for (int o = 16; o > 0; o >>= 1)
        lsum += __shfl_down_sync(0xffffffffu, lsum, o);
    if ((tid & 31) == 0) s_red[tid >> 5] = lsum;
    __syncthreads();
    if (tid == 0) {
        float v = 0.0f;
        #pragma unroll
        for (int w = 0; w < 8; w++) v += s_red[w];
        // Fixed-point RED.ADD.u64: fire-and-forget, associative, deterministic.
        atomicAdd(&g_isum, (unsigned long long)__double2ll_rn((double)v * FXSCALE));
    }
}

// Trivial finalize: one load, one store, reset accumulator for graph replay.
__global__ void ssim_finalize(float* __restrict__ out)
{
    const double s = (double)g_isum * (1.0 / FXSCALE);
    out[0] = 1.0f - (float)(s / NPIX);
    g_isum = 0ULL;
}

extern "C" void kernel_launch(void* const* d_in, const int* in_sizes, int n_in,
                              void* d_out, int out_size)
{
    const float* pred = (const float*)d_in[0];
    const float* targ = (const float*)d_in[1];
    dim3 grid(TILES_X, TILES_Y, NPLANES);
    ssim_main<<<grid, NTHREADS>>>(pred, targ);
    ssim_finalize<<<1, 1>>>((float*)d_out);
}

// round 12
// speedup vs baseline: 1.0836x; 1.0565x over previous
#include <cuda_runtime.h>

// SSIM loss: pred/target fp32 (8,8,3,256,256) -> scalar 1 - mean(ssim_map)
// 192 planes of 256x256. Depthwise 11x11 Gaussian (sigma=1.5), separable.
//
// Sum/diff basis: s = x+y, d = x-y. Four convolutions (s, d, s^2, d^2),
// computed PAIRWISE with fma.rn.f32x2: stream S = (conv s, conv s^2),
// stream D = (conv d, conv d^2). Packing is (value, value^2) per stream, so
// warp smem access stays dense (R5's column-pair packing made it sparse).
//   A = conv(s), B = conv(d), S1 = conv(s^2), S2 = conv(d^2)
//   4 mu_xy = A^2 - B^2;  2(mu_x^2+mu_y^2) = A^2 + B^2
//   4 Sxy   = S1 - S2;    2(Sxx+Syy)       = S1 + S2
//
// Global reduction: fixed-point u64 RED.ADD (associative -> deterministic,
// fire-and-forget -> no per-block fence; a fence/release costs +20us here).

#define HW       256
#define PLANE    (HW * HW)
#define NPLANES  192
#define TILES_X  8
#define TILES_Y  8
#define NTHREADS 256
#define NPIX     12582912.0                       // 192*256*256
#define FXSCALE  4294967296.0                     // 2^32

#define ROWW     48                               // staged raw row width (floats)
#define NROWS    42                               // 32 out + 2*5 halo

__device__ unsigned long long g_isum = 0ULL;      // reset by finalize (replay-safe)

// Normalized Gaussian weights for ws=11, sigma=1.5.
#define GW0 0.00102838f
#define GW1 0.00759872f
#define GW2 0.03600084f
#define GW3 0.10936034f
#define GW4 0.21300566f
#define GW5 0.26601220f

typedef unsigned long long ull;

__device__ __forceinline__ void fma2(ull& d, ull a, ull b) {
    asm("fma.rn.f32x2 %0, %1, %2, %0;" : "+l"(d) : "l"(a), "l"(b));
}
__device__ __forceinline__ ull pack2(float lo, float hi) {
    ull r; asm("mov.b64 %0, {%1, %2};" : "=l"(r) : "f"(lo), "f"(hi)); return r;
}
__device__ __forceinline__ void unpack2(float& lo, float& hi, ull v) {
    asm("mov.b64 {%0, %1}, %2;" : "=f"(lo), "=f"(hi) : "l"(v));
}

__global__ __launch_bounds__(NTHREADS, 6) void ssim_main(
    const float* __restrict__ pred, const float* __restrict__ targ)
{
    // Pair streams: (convS, convS2) and (convD, convD2), 42 rows x 32 cols.
    __shared__ float s_sp[NROWS * 64];            // 10752 B
    __shared__ float s_dp[NROWS * 64];            // 10752 B
    __shared__ float s_raw[2][NROWS * ROWW];      // 16128 B (s, d), zero-padded
    __shared__ float s_red[8];

    const int tid = threadIdx.x;
    const int ox = blockIdx.x * 32;
    const int oy = blockIdx.y * 32;
    const int plane = blockIdx.z;
    const float* __restrict__ px = pred + (size_t)plane * PLANE;
    const float* __restrict__ py = targ + (size_t)plane * PLANE;

    ull W2[6];
    W2[0] = pack2(GW0, GW0); W2[1] = pack2(GW1, GW1); W2[2] = pack2(GW2, GW2);
    W2[3] = pack2(GW3, GW3); W2[4] = pack2(GW4, GW4); W2[5] = pack2(GW5, GW5);

    // ---- Phase 0: coalesced float4 staging of s = x+y, d = x-y ----
    // 42 rows x 12 float4 = 504 tasks. smem col j <-> gmem col ox-8+j.
    for (int task = tid; task < NROWS * 12; task += NTHREADS) {
        const int r  = task / 12;
        const int v  = task - r * 12;
        const int gy = oy + r - 5;
        const int gx = ox - 8 + 4 * v;

        float4 xv = make_float4(0.f, 0.f, 0.f, 0.f);
        float4 yv = xv;
        if ((unsigned)gy < (unsigned)HW && (unsigned)gx < (unsigned)HW) {
            xv = __ldg(reinterpret_cast<const float4*>(px + gy * HW + gx));
            yv = __ldg(reinterpret_cast<const float4*>(py + gy * HW + gx));
        }
        const int o = r * ROWW + 4 * v;
        *reinterpret_cast<float4*>(&s_raw[0][o]) =
            make_float4(xv.x + yv.x, xv.y + yv.y, xv.z + yv.z, xv.w + yv.w);
        *reinterpret_cast<float4*>(&s_raw[1][o]) =
            make_float4(xv.x - yv.x, xv.y - yv.y, xv.z - yv.z, xv.w - yv.w);
    }
    __syncthreads();

    // ---- Phase A: horizontal conv, packed (value, value^2) per stream ----
    // 42 rows x 8 col-groups (4 outputs) = 336 tasks.
    for (int task = tid; task < NROWS * 8; task += NTHREADS) {
        const int r  = task >> 3;
        const int c0 = (task & 7) * 4;
        const int base = r * ROWW + c0;

        #pragma unroll
        for (int arr = 0; arr < 2; arr++) {
            float t[20];
            #pragma unroll
            for (int vi = 0; vi < 5; vi++)
                *reinterpret_cast<float4*>(&t[4 * vi]) =
                    *reinterpret_cast<const float4*>(&s_raw[arr][base + 4 * vi]);

            ull acc[4] = {0ULL, 0ULL, 0ULL, 0ULL};
            #pragma unroll
            for (int m = 0; m < 14; m++) {
                const float tv = t[3 + m];
                const ull p = pack2(tv, tv * tv);
                #pragma unroll
                for (int j = 0; j < 4; j++) {
                    const int k = m - j;
                    if (k >= 0 && k <= 10)
                        fma2(acc[j], p, W2[(k < 6) ? k : 10 - k]);
                }
            }
            float* dst = arr ? s_dp : s_sp;
            ulonglong2 st0; st0.x = acc[0]; st0.y = acc[1];
            ulonglong2 st1; st1.x = acc[2]; st1.y = acc[3];
            *reinterpret_cast<ulonglong2*>(&dst[(r * 32 + c0) * 2])     = st0;
            *reinterpret_cast<ulonglong2*>(&dst[(r * 32 + c0 + 2) * 2]) = st1;
        }
    }
    __syncthreads();

    // ---- Phase B+C: packed vertical conv (4 rows) then SSIM directly ----
    // 256 tasks: tid -> (rowgroup of 4, col).
    float lsum = 0.0f;
    {
        const int rg = tid >> 5;          // 0..7
        const int c  = tid & 31;
        const int r0 = rg * 4;

        ull aS[4] = {0ULL, 0ULL, 0ULL, 0ULL};
        ull aD[4] = {0ULL, 0ULL, 0ULL, 0ULL};
        #pragma unroll
        for (int k = 0; k < 14; k++) {
            const ull vs = *reinterpret_cast<const ull*>(&s_sp[((r0 + k) * 32 + c) * 2]);
            const ull vd = *reinterpret_cast<const ull*>(&s_dp[((r0 + k) * 32 + c) * 2]);
            #pragma unroll
            for (int j = 0; j < 4; j++) {
                const int kk = k - j;
                if (kk >= 0 && kk <= 10) {
                    const int wk = (kk < 6) ? kk : 10 - kk;
                    fma2(aS[j], vs, W2[wk]);
                    fma2(aD[j], vd, W2[wk]);
                }
            }
        }

        #pragma unroll
        for (int j = 0; j < 4; j++) {
            float A, S1, B, S2;
            unpack2(A, S1, aS[j]);
            unpack2(B, S2, aD[j]);

            const float A2 = A * A;
            const float B2 = B * B;
            const float mxy  = 0.25f * (A2 - B2);          // mu_x * mu_y
            const float msum = 0.50f * (A2 + B2);          // mu_x^2 + mu_y^2
            const float sxy  = 0.25f * (S1 - S2) - mxy;    // sigma_xy
            const float ssum = fmaxf(0.50f * (S1 + S2) - msum, 0.0f);

            // den >= C1*C2 > 0 always; reference's nan_to_num is a no-op for
            // bounded inputs. Fast divide: 2^-21 rel err << 1e-3 budget.
            const float num = (2.0f * mxy + 1e-4f) * (2.0f * sxy + 9e-4f);
            const float den = (msum + 1e-4f) * (ssum + 9e-4f);
            lsum += __fdividef(num, den + 1e-8f);
        }
    }

    #pragma unroll
    for (int o = 16; o > 0; o >>= 1)
        lsum += __shfl_down_sync(0xffffffffu, lsum, o);
    if ((tid & 31) == 0) s_red[tid >> 5] = lsum;
    __syncthreads();
    if (tid == 0) {
        float v = 0.0f;
        #pragma unroll
        for (int w = 0; w < 8; w++) v += s_red[w];
        // Fixed-point RED.ADD.u64: fire-and-forget, associative, deterministic.
        atomicAdd(&g_isum, (unsigned long long)__double2ll_rn((double)v * FXSCALE));
    }
}

// Trivial finalize: one load, one store, reset accumulator for graph replay.
__global__ void ssim_finalize(float* __restrict__ out)
{
    const double s = (double)g_isum * (1.0 / FXSCALE);
    out[0] = 1.0f - (float)(s / NPIX);
    g_isum = 0ULL;
}

extern "C" void kernel_launch(void* const* d_in, const int* in_sizes, int n_in,
                              void* d_out, int out_size)
{
    const float* pred = (const float*)d_in[0];
    const float* targ = (const float*)d_in[1];
    dim3 grid(TILES_X, TILES_Y, NPLANES);
    ssim_main<<<grid, NTHREADS>>>(pred, targ);
    ssim_finalize<<<1, 1>>>((float*)d_out);
}